// round 3
// baseline (speedup 1.0000x reference)
#include <cuda_runtime.h>
#include <cuda_bf16.h>
#include <cstdint>
#include <cstddef>

// Problem dims (fixed by reference)
#define TDIM 1024
#define BDIM 32
#define DIN  256
#define HDIM 256
#define AADIM 21

// Scratch (device globals: allocation-guard safe)
// U layout PERMUTED: (T, B, dir, H, 4)  — float4 per (t,b,dir,h)
__device__ float g_U [ (size_t)TDIM * BDIM * 8 * HDIM ];   // 256 MB
__device__ float g_H0[ (size_t)TDIM * BDIM * 2 * HDIM ];   // 64 MB   (T,B,2H)
__device__ float g_H1[ (size_t)TDIM * BDIM * 2 * HDIM ];   // 64 MB
__device__ float g_Y [ (size_t)TDIM * BDIM * HDIM ];       // 32 MB   (T*B, H)
__device__ float g_WT[ 2 * HDIM * HDIM ];                  // fc1_w^T (512,256)

__device__ __forceinline__ uint32_t f2tf(float f) {
    uint32_t u;
    asm("cvt.rna.tf32.f32 %0, %1;" : "=r"(u) : "f"(f));
    return u;
}

// ---------------------------------------------------------------------------
// TF32 tensor-core GEMM, double-buffered (BK=16, 2 stages), BM=BN=128,
// 256 threads = 8 warps (2x4), warp tile 64x32, mma.m16n8k8.tf32.
// XMODE: A row m -> x[b][t] (x is (B,T,K)).
// UPERM: output columns permuted p = dir*1024 + h*4 + k (n = dir*1024+k*256+h);
//        B loader reads the logical n for permuted column p; C store is
//        contiguous in permuted space.
// ---------------------------------------------------------------------------
#define LDA 137
#define LDB 136
#define BK  16

template<bool XMODE, bool UPERM>
__global__ __launch_bounds__(256)
void tf32_gemm(const float* __restrict__ A, const float* __restrict__ Bm,
               float* __restrict__ C, int M, int N, int K,
               const float* __restrict__ bias)
{
    __shared__ uint32_t As[2 * BK * LDA];   // [stage][k][m]
    __shared__ uint32_t Bs[2 * BK * LDB];   // [stage][k][n]

    const int tid  = threadIdx.x;
    const int lane = tid & 31;
    const int wid  = tid >> 5;
    const int bm = blockIdx.y * 128;
    const int bn = blockIdx.x * 128;
    const int wm = (wid & 1) * 64;
    const int wn = (wid >> 1) * 32;

    float acc[4][4][4];
    #pragma unroll
    for (int mi = 0; mi < 4; mi++)
        #pragma unroll
        for (int ni = 0; ni < 4; ni++)
            #pragma unroll
            for (int r = 0; r < 4; r++)
                acc[mi][ni][r] = 0.f;

    // A-load: 128 rows x 16 k; thread does 2 float4 along K
    const int ar0 = tid >> 2;            // 0..63 (rows ar0, ar0+64)
    const int akq = (tid & 3) * 4;       // 0,4,8,12
    // B-load (standard): 16 k-rows x 128 n; thread does 2 float4 along N
    const int bkr = tid >> 5;            // 0..7 (k-rows bkr, bkr+8)
    const int bnc = (tid & 31) * 4;
    // B-load (UPERM): permuted-space decoding of bn
    const int dirbase = (bn >> 10) * 1024;
    const int h0      = (bn & 1023) >> 2;       // multiple of 32

    const int g2 = lane >> 2;            // 0..7
    const int g4 = lane & 3;             // 0..3

    float4 ra[2];
    float4 rbv[2];
    float  rb8[8];

    // ---- prefetch helpers (inline) ----
    #define LDG_TILE(k0v)                                                     \
    {                                                                         \
        _Pragma("unroll")                                                     \
        for (int p = 0; p < 2; p++) {                                         \
            int r  = ar0 + p * 64;                                            \
            int gm = bm + r;                                                  \
            size_t off;                                                       \
            if (XMODE) {                                                      \
                int t  = gm >> 5;                                             \
                int bb = gm & 31;                                             \
                off = ((size_t)bb * TDIM + t) * (size_t)K + (k0v) + akq;      \
            } else {                                                          \
                off = (size_t)gm * K + (k0v) + akq;                           \
            }                                                                 \
            ra[p] = *(const float4*)(A + off);                                \
        }                                                                     \
        if (UPERM) {                                                          \
            _Pragma("unroll")                                                 \
            for (int p = 0; p < 2; p++) {                                     \
                int kr = bkr + p * 8;                                         \
                _Pragma("unroll")                                             \
                for (int k = 0; k < 4; k++)                                   \
                    rb8[p * 4 + k] =                                          \
                        Bm[(size_t)((k0v) + kr) * N + dirbase + k * 256 + h0 + lane]; \
            }                                                                 \
        } else {                                                              \
            _Pragma("unroll")                                                 \
            for (int p = 0; p < 2; p++) {                                     \
                int kr = bkr + p * 8;                                         \
                rbv[p] = *(const float4*)(Bm + (size_t)((k0v) + kr) * N + bn + bnc); \
            }                                                                 \
        }                                                                     \
    }

    #define STS_TILE(buf)                                                     \
    {                                                                         \
        uint32_t* Ab = As + (buf) * (BK * LDA);                               \
        uint32_t* Bb = Bs + (buf) * (BK * LDB);                               \
        _Pragma("unroll")                                                     \
        for (int p = 0; p < 2; p++) {                                         \
            int r = ar0 + p * 64;                                             \
            Ab[(akq + 0) * LDA + r] = f2tf(ra[p].x);                          \
            Ab[(akq + 1) * LDA + r] = f2tf(ra[p].y);                          \
            Ab[(akq + 2) * LDA + r] = f2tf(ra[p].z);                          \
            Ab[(akq + 3) * LDA + r] = f2tf(ra[p].w);                          \
        }                                                                     \
        if (UPERM) {                                                          \
            _Pragma("unroll")                                                 \
            for (int p = 0; p < 2; p++) {                                     \
                int kr = bkr + p * 8;                                         \
                _Pragma("unroll")                                             \
                for (int k = 0; k < 4; k++)                                   \
                    Bb[kr * LDB + lane * 4 + k] = f2tf(rb8[p * 4 + k]);       \
            }                                                                 \
        } else {                                                              \
            _Pragma("unroll")                                                 \
            for (int p = 0; p < 2; p++) {                                     \
                int kr = bkr + p * 8;                                         \
                Bb[kr * LDB + bnc + 0] = f2tf(rbv[p].x);                      \
                Bb[kr * LDB + bnc + 1] = f2tf(rbv[p].y);                      \
                Bb[kr * LDB + bnc + 2] = f2tf(rbv[p].z);                      \
                Bb[kr * LDB + bnc + 3] = f2tf(rbv[p].w);                      \
            }                                                                 \
        }                                                                     \
    }

    // prologue: tile 0 -> buf 0
    LDG_TILE(0);
    STS_TILE(0);
    __syncthreads();

    for (int k0 = 0; k0 < K; k0 += BK) {
        const int cur = (k0 >> 4) & 1;
        const int nxt = cur ^ 1;
        const bool has_next = (k0 + BK) < K;

        if (has_next) LDG_TILE(k0 + BK);

        const uint32_t* Ab = As + cur * (BK * LDA);
        const uint32_t* Bb = Bs + cur * (BK * LDB);

        #pragma unroll
        for (int kk = 0; kk < 2; kk++) {
            const int kb = kk * 8;
            uint32_t af[4][4], bfr[4][2];
            #pragma unroll
            for (int mi = 0; mi < 4; mi++) {
                int r = wm + mi * 16 + g2;
                af[mi][0] = Ab[(kb + g4) * LDA + r];
                af[mi][1] = Ab[(kb + g4) * LDA + r + 8];
                af[mi][2] = Ab[(kb + g4 + 4) * LDA + r];
                af[mi][3] = Ab[(kb + g4 + 4) * LDA + r + 8];
            }
            #pragma unroll
            for (int ni = 0; ni < 4; ni++) {
                int cn = wn + ni * 8 + g2;
                bfr[ni][0] = Bb[(kb + g4) * LDB + cn];
                bfr[ni][1] = Bb[(kb + g4 + 4) * LDB + cn];
            }
            #pragma unroll
            for (int mi = 0; mi < 4; mi++)
                #pragma unroll
                for (int ni = 0; ni < 4; ni++) {
                    asm volatile(
                        "mma.sync.aligned.m16n8k8.row.col.f32.tf32.tf32.f32 "
                        "{%0,%1,%2,%3}, {%4,%5,%6,%7}, {%8,%9}, {%0,%1,%2,%3};"
                        : "+f"(acc[mi][ni][0]), "+f"(acc[mi][ni][1]),
                          "+f"(acc[mi][ni][2]), "+f"(acc[mi][ni][3])
                        : "r"(af[mi][0]), "r"(af[mi][1]),
                          "r"(af[mi][2]), "r"(af[mi][3]),
                          "r"(bfr[ni][0]), "r"(bfr[ni][1]));
                }
        }

        if (has_next) STS_TILE(nxt);
        __syncthreads();
    }

    #undef LDG_TILE
    #undef STS_TILE

    // ---- store C (+bias); columns are permuted-space when UPERM but the
    //      store expression is identical (contiguous in that space).
    #pragma unroll
    for (int mi = 0; mi < 4; mi++) {
        int row0 = bm + wm + mi * 16 + g2;
        #pragma unroll
        for (int ni = 0; ni < 4; ni++) {
            int col = bn + wn + ni * 8 + 2 * g4;
            float bx = 0.f, by = 0.f;
            if (bias) { bx = bias[col]; by = bias[col + 1]; }
            float2 v0 = make_float2(acc[mi][ni][0] + bx, acc[mi][ni][1] + by);
            float2 v1 = make_float2(acc[mi][ni][2] + bx, acc[mi][ni][3] + by);
            *(float2*)(C + (size_t)row0 * N + col)       = v0;
            *(float2*)(C + (size_t)(row0 + 8) * N + col) = v1;
        }
    }
}

// ---------------------------------------------------------------------------
// SRU scan, float4 U layout (T,B,dir,H,4), depth-16 register ring buffer.
// One thread per (dir,b,h); 64 threads/block, 256 blocks.
// ---------------------------------------------------------------------------
#define SCAN_D 16

__global__ __launch_bounds__(64)
void sru_scan_kernel(const float4* __restrict__ U4, const float* __restrict__ wc,
                     const float* __restrict__ bvec, float* __restrict__ Hout)
{
    const int q   = HDIM / 64;                       // 4
    const int bi  = blockIdx.x;
    const int dir = bi / (BDIM * q);
    const int b   = (bi / q) % BDIM;
    const int h   = (bi % q) * 64 + threadIdx.x;

    const float vf = wc[(dir * 2 + 0) * HDIM + h];
    const float vr = wc[(dir * 2 + 1) * HDIM + h];
    const float bf = bvec[(dir * 2 + 0) * HDIM + h];
    const float br = bvec[(dir * 2 + 1) * HDIM + h];

    const int t0 = dir ? (TDIM - 1) : 0;
    const long dt = dir ? -1 : 1;

    const float4* up = U4 + (((size_t)t0 * BDIM + b) * 2 + dir) * HDIM + h;
    float* hp = Hout + ((size_t)t0 * BDIM + b) * (2 * HDIM)
                     + (size_t)dir * HDIM + h;
    const long ustep = dt * (long)BDIM * 2 * HDIM;    // float4 units
    const long hstep = dt * (long)BDIM * 2 * HDIM;    // float units

    float4 ring[SCAN_D];
    const float4* lp = up;
    #pragma unroll
    for (int d = 0; d < SCAN_D; d++) { ring[d] = *lp; lp += ustep; }

    float c = 0.f;
    for (int s0 = 0; s0 < TDIM; s0 += SCAN_D) {
        #pragma unroll
        for (int d = 0; d < SCAN_D; d++) {
            float4 u = ring[d];
            if (s0 + d + SCAN_D < TDIM) { ring[d] = *lp; lp += ustep; }
            float f  = 1.f / (1.f + __expf(-(u.y + vf * c + bf)));
            float c2 = f * c + (1.f - f) * u.x;
            float r  = 1.f / (1.f + __expf(-(u.z + vr * c + br)));
            float hv = r * c2 + (1.f - r) * u.w;
            c = c2;
            *hp = hv;
            hp += hstep;
        }
    }
}

// ---------------------------------------------------------------------------
// Transpose fc1_w (H, 2H) -> WT (2H, H)
// ---------------------------------------------------------------------------
__global__ void transpose_fc1(const float* __restrict__ w, float* __restrict__ wt)
{
    int idx = blockIdx.x * blockDim.x + threadIdx.x;
    int total = HDIM * 2 * HDIM;
    if (idx < total) {
        int r = idx / (2 * HDIM);
        int c = idx % (2 * HDIM);
        wt[(size_t)c * HDIM + r] = w[idx];
    }
}

// ---------------------------------------------------------------------------
// logits = log_softmax(Y @ lp_w^T + lp_b). 4 rows per warp, 32 rows/block.
// ---------------------------------------------------------------------------
__global__ __launch_bounds__(256)
void logits_kernel(const float* __restrict__ Y, const float* __restrict__ lp_w,
                   const float* __restrict__ lp_b, float* __restrict__ out)
{
    __shared__ float ws[AADIM * HDIM];
    __shared__ float bs[32];
    const int tid = threadIdx.x;
    for (int i = tid; i < AADIM * HDIM; i += blockDim.x) ws[i] = lp_w[i];
    if (tid < AADIM) bs[tid] = lp_b[tid];
    __syncthreads();

    const int warp = tid >> 5;
    const int lane = tid & 31;

    #pragma unroll
    for (int rr = 0; rr < 4; rr++) {
        const int row = blockIdx.x * 32 + warp * 4 + rr;   // row = t*B + b
        const int t = row / BDIM;
        const int b = row % BDIM;

        const float* y = Y + (size_t)row * HDIM;
        float yv[8];
        #pragma unroll
        for (int i = 0; i < 8; i++) yv[i] = y[lane + 32 * i];

        float lg[AADIM];
        #pragma unroll
        for (int a = 0; a < AADIM; a++) {
            float s = 0.f;
            #pragma unroll
            for (int i = 0; i < 8; i++) s += yv[i] * ws[a * HDIM + lane + 32 * i];
            #pragma unroll
            for (int off = 16; off > 0; off >>= 1)
                s += __shfl_xor_sync(0xFFFFFFFFu, s, off);
            lg[a] = s + bs[a];
        }

        float mx = lg[0];
        #pragma unroll
        for (int a = 1; a < AADIM; a++) mx = fmaxf(mx, lg[a]);
        float se = 0.f;
        #pragma unroll
        for (int a = 0; a < AADIM; a++) se += __expf(lg[a] - mx);
        float lse = mx + __logf(se);

        float myv = 0.f;
        #pragma unroll
        for (int a = 0; a < AADIM; a++) if (lane == a) myv = lg[a] - lse;
        if (lane < AADIM)
            out[((size_t)b * TDIM + t) * AADIM + lane] = myv;
    }
}

// ---------------------------------------------------------------------------
extern "C" void kernel_launch(void* const* d_in, const int* in_sizes, int n_in,
                              void* d_out, int out_size)
{
    const float* x     = (const float*)d_in[0];
    // d_in[1] = hidden (unused)
    const float* w_l0  = (const float*)d_in[2];
    const float* wc_l0 = (const float*)d_in[3];
    const float* b_l0  = (const float*)d_in[4];
    const float* w_l1  = (const float*)d_in[5];
    const float* wc_l1 = (const float*)d_in[6];
    const float* b_l1  = (const float*)d_in[7];
    const float* fc1_w = (const float*)d_in[8];
    const float* fc1_b = (const float*)d_in[9];
    const float* lp_w  = (const float*)d_in[10];
    const float* lp_b  = (const float*)d_in[11];
    float* out = (float*)d_out;

    float *pU, *pH0, *pH1, *pY, *pWT;
    cudaGetSymbolAddress((void**)&pU,  g_U);
    cudaGetSymbolAddress((void**)&pH0, g_H0);
    cudaGetSymbolAddress((void**)&pH1, g_H1);
    cudaGetSymbolAddress((void**)&pY,  g_Y);
    cudaGetSymbolAddress((void**)&pWT, g_WT);

    const int M = TDIM * BDIM;      // 32768

    // transpose fc1_w -> WT (off the hot path conceptually; serialized anyway)
    transpose_fc1<<<(HDIM * 2 * HDIM + 255) / 256, 256>>>(fc1_w, pWT);

    // GEMM1: U0 = x(T,B view) @ w_l0  [32768 x 2048 x 256], permuted output
    {
        dim3 grid(2048 / 128, M / 128);
        tf32_gemm<true, true><<<grid, 256>>>(x, w_l0, pU, M, 2048, DIN, nullptr);
    }
    // scan layer 0 -> H0
    sru_scan_kernel<<<2 * BDIM * (HDIM / 64), 64>>>((const float4*)pU, wc_l0, b_l0, pH0);

    // GEMM2: U1 = H0 @ w_l1  [32768 x 2048 x 512], permuted output
    {
        dim3 grid(2048 / 128, M / 128);
        tf32_gemm<false, true><<<grid, 256>>>(pH0, w_l1, pU, M, 2048, 2 * HDIM, nullptr);
    }
    // scan layer 1 -> H1
    sru_scan_kernel<<<2 * BDIM * (HDIM / 64), 64>>>((const float4*)pU, wc_l1, b_l1, pH1);

    // GEMM3: Y = H1 @ WT + fc1_b  [32768 x 256 x 512]
    {
        dim3 grid(HDIM / 128, M / 128);
        tf32_gemm<false, false><<<grid, 256>>>(pH1, pWT, pY, M, HDIM, 2 * HDIM, fc1_b);
    }

    // logits + log_softmax
    logits_kernel<<<M / 32, 256>>>(pY, lp_w, lp_b, out);
}

// round 4
// speedup vs baseline: 1.0740x; 1.0740x over previous
#include <cuda_runtime.h>
#include <cuda_bf16.h>
#include <cstdint>
#include <cstddef>

// Problem dims (fixed by reference)
#define TDIM 1024
#define BDIM 32
#define DIN  256
#define HDIM 256
#define AADIM 21

// Scratch (device globals: allocation-guard safe)
// U layout PERMUTED: (T, B, dir, H, 4) — float4 per (t,b,dir,h)
__device__ float g_U  [ (size_t)TDIM * BDIM * 8 * HDIM ];   // 256 MB
__device__ float g_H0 [ (size_t)TDIM * BDIM * 2 * HDIM ];   // 64 MB (T,B,2H)
__device__ float g_H1 [ (size_t)TDIM * BDIM * 2 * HDIM ];   // 64 MB
__device__ float g_Y  [ (size_t)TDIM * BDIM * HDIM ];       // 32 MB (T*B, H)
__device__ float g_WT [ 2 * HDIM * HDIM ];                  // fc1_w^T (512,256)
__device__ float g_WP0[ DIN * 2048 ];                       // w_l0 col-permuted
__device__ float g_WP1[ 2 * HDIM * 2048 ];                  // w_l1 col-permuted

// ---------------------------------------------------------------------------
// GEMM: C[M,N] = A[M,K] @ B[K,N] (+bias), tf32 mma m16n8k8 (truncated fp32).
// Block 128x128, 128 threads = 4 warps (2x2), warp tile 64x64.
// cp.async 3-stage pipeline, BK=16.
// XMODE: A row m -> x[b][t] with t=m/32, b=m%32 (x is (B,T,K)).
// ---------------------------------------------------------------------------
#define BK     16
#define LDAK   20                 // floats per A smem row (16 data + 4 pad)
#define LDBN   136                // floats per B smem k-row (128 data + 8 pad)
#define STAGEF (128 * LDAK + BK * LDBN)   // 4736 floats per stage
#define GSMEM  (3 * STAGEF * 4)           // 56832 bytes

__device__ __forceinline__ void cp16(uint32_t dst, const float* src) {
    asm volatile("cp.async.cg.shared.global [%0], [%1], 16;"
                 :: "r"(dst), "l"(src));
}

template<bool XMODE>
__global__ __launch_bounds__(128)
void tf32_gemm(const float* __restrict__ A, const float* __restrict__ Bm,
               float* __restrict__ C, int M, int N, int K,
               const float* __restrict__ bias)
{
    extern __shared__ float smem[];

    const int tid  = threadIdx.x;
    const int lane = tid & 31;
    const int wid  = tid >> 5;
    const int bm = blockIdx.y * 128;
    const int bn = blockIdx.x * 128;
    const int wm = (wid & 1) * 64;
    const int wn = (wid >> 1) * 64;
    const int g2 = lane >> 2;     // 0..7
    const int g4 = lane & 3;      // 0..3

    float acc[4][8][4];
    #pragma unroll
    for (int mi = 0; mi < 4; mi++)
        #pragma unroll
        for (int ni = 0; ni < 8; ni++)
            #pragma unroll
            for (int r = 0; r < 4; r++)
                acc[mi][ni][r] = 0.f;

    // A source base: thread owns tile-row tid
    size_t a_base;
    {
        int gm = bm + tid;
        if (XMODE) {
            int t  = gm >> 5;
            int bb = gm & 31;
            a_base = ((size_t)bb * TDIM + t) * (size_t)K;
        } else {
            a_base = (size_t)gm * K;
        }
    }

    const int T_t = K >> 4;   // tiles

    // issue one tile's cp.asyncs into stage buffer
    #define ISSUE(tile, buf)                                                  \
    {                                                                         \
        float* As_ = smem + (buf) * STAGEF;                                   \
        float* Bs_ = As_ + 128 * LDAK;                                        \
        const int k0_ = (tile) * BK;                                          \
        uint32_t adst = (uint32_t)__cvta_generic_to_shared(As_ + tid * LDAK); \
        _Pragma("unroll")                                                     \
        for (int c = 0; c < 4; c++)                                           \
            cp16(adst + c * 16, A + a_base + k0_ + c * 4);                    \
        _Pragma("unroll")                                                     \
        for (int p = 0; p < 4; p++) {                                         \
            int id = tid + p * 128;                                           \
            int kr = id >> 5;                                                 \
            int cc = (id & 31) * 4;                                           \
            uint32_t bdst = (uint32_t)__cvta_generic_to_shared(               \
                Bs_ + kr * LDBN + cc);                                        \
            cp16(bdst, Bm + (size_t)(k0_ + kr) * N + bn + cc);                \
        }                                                                     \
        asm volatile("cp.async.commit_group;");                               \
    }

    ISSUE(0, 0);
    ISSUE(1, 1);

    for (int t = 0; t < T_t; t++) {
        if (t + 1 < T_t) asm volatile("cp.async.wait_group 1;");
        else             asm volatile("cp.async.wait_group 0;");
        __syncthreads();

        if (t + 2 < T_t) { int nb = (t + 2) % 3; ISSUE(t + 2, nb); }

        const float* As_ = smem + (t % 3) * STAGEF;
        const float* Bs_ = As_ + 128 * LDAK;

        #pragma unroll
        for (int kk = 0; kk < 2; kk++) {
            const int kb = kk * 8;
            uint32_t af[4][4];
            #pragma unroll
            for (int mi = 0; mi < 4; mi++) {
                int r = wm + mi * 16 + g2;
                af[mi][0] = __float_as_uint(As_[r * LDAK + kb + g4]);
                af[mi][1] = __float_as_uint(As_[(r + 8) * LDAK + kb + g4]);
                af[mi][2] = __float_as_uint(As_[r * LDAK + kb + g4 + 4]);
                af[mi][3] = __float_as_uint(As_[(r + 8) * LDAK + kb + g4 + 4]);
            }
            #pragma unroll
            for (int ni = 0; ni < 8; ni++) {
                int cn = wn + ni * 8 + g2;
                uint32_t b0 = __float_as_uint(Bs_[(kb + g4) * LDBN + cn]);
                uint32_t b1 = __float_as_uint(Bs_[(kb + g4 + 4) * LDBN + cn]);
                #pragma unroll
                for (int mi = 0; mi < 4; mi++) {
                    asm volatile(
                        "mma.sync.aligned.m16n8k8.row.col.f32.tf32.tf32.f32 "
                        "{%0,%1,%2,%3}, {%4,%5,%6,%7}, {%8,%9}, {%0,%1,%2,%3};"
                        : "+f"(acc[mi][ni][0]), "+f"(acc[mi][ni][1]),
                          "+f"(acc[mi][ni][2]), "+f"(acc[mi][ni][3])
                        : "r"(af[mi][0]), "r"(af[mi][1]),
                          "r"(af[mi][2]), "r"(af[mi][3]),
                          "r"(b0), "r"(b1));
                }
            }
        }
    }
    #undef ISSUE

    // store C (+bias)
    #pragma unroll
    for (int mi = 0; mi < 4; mi++) {
        int row0 = bm + wm + mi * 16 + g2;
        #pragma unroll
        for (int ni = 0; ni < 8; ni++) {
            int col = bn + wn + ni * 8 + 2 * g4;
            float bx = 0.f, by = 0.f;
            if (bias) { bx = bias[col]; by = bias[col + 1]; }
            float2 v0 = make_float2(acc[mi][ni][0] + bx, acc[mi][ni][1] + by);
            float2 v1 = make_float2(acc[mi][ni][2] + bx, acc[mi][ni][3] + by);
            *(float2*)(C + (size_t)row0 * N + col)       = v0;
            *(float2*)(C + (size_t)(row0 + 8) * N + col) = v1;
        }
    }
}

// ---------------------------------------------------------------------------
// Permute weight columns: wp[k][p] = w[k][n], p = dir*1024 + h*4 + kk,
// n = dir*1024 + kk*256 + h. Makes GEMM output land in (…,dir,H,4) layout.
// ---------------------------------------------------------------------------
__global__ void permute_w(const float* __restrict__ w, float* __restrict__ wp,
                          int K)
{
    int idx = blockIdx.x * blockDim.x + threadIdx.x;
    if (idx >= K * 2048) return;
    int k = idx >> 11;
    int n = idx & 2047;
    int dir = n >> 10;
    int r   = n & 1023;
    int kk  = r >> 8;
    int h   = r & 255;
    int p = dir * 1024 + h * 4 + kk;
    wp[(size_t)k * 2048 + p] = w[idx];
}

// ---------------------------------------------------------------------------
// SRU scan, float4 U layout (T,B,dir,H,4), depth-16 register ring buffer.
// ---------------------------------------------------------------------------
#define SCAN_D 16

__global__ __launch_bounds__(64)
void sru_scan_kernel(const float4* __restrict__ U4, const float* __restrict__ wc,
                     const float* __restrict__ bvec, float* __restrict__ Hout)
{
    const int q   = HDIM / 64;                       // 4
    const int bi  = blockIdx.x;
    const int dir = bi / (BDIM * q);
    const int b   = (bi / q) % BDIM;
    const int h   = (bi % q) * 64 + threadIdx.x;

    const float vf = wc[(dir * 2 + 0) * HDIM + h];
    const float vr = wc[(dir * 2 + 1) * HDIM + h];
    const float bf = bvec[(dir * 2 + 0) * HDIM + h];
    const float br = bvec[(dir * 2 + 1) * HDIM + h];

    const int t0 = dir ? (TDIM - 1) : 0;
    const long dt = dir ? -1 : 1;

    const float4* up = U4 + (((size_t)t0 * BDIM + b) * 2 + dir) * HDIM + h;
    float* hp = Hout + ((size_t)t0 * BDIM + b) * (2 * HDIM)
                     + (size_t)dir * HDIM + h;
    const long ustep = dt * (long)BDIM * 2 * HDIM;    // float4 units
    const long hstep = dt * (long)BDIM * 2 * HDIM;    // float units

    float4 ring[SCAN_D];
    const float4* lp = up;
    #pragma unroll
    for (int d = 0; d < SCAN_D; d++) { ring[d] = *lp; lp += ustep; }

    float c = 0.f;
    for (int s0 = 0; s0 < TDIM; s0 += SCAN_D) {
        #pragma unroll
        for (int d = 0; d < SCAN_D; d++) {
            float4 u = ring[d];
            if (s0 + d + SCAN_D < TDIM) { ring[d] = *lp; lp += ustep; }
            float f  = 1.f / (1.f + __expf(-(u.y + vf * c + bf)));
            float c2 = f * c + (1.f - f) * u.x;
            float r  = 1.f / (1.f + __expf(-(u.z + vr * c + br)));
            float hv = r * c2 + (1.f - r) * u.w;
            c = c2;
            *hp = hv;
            hp += hstep;
        }
    }
}

// ---------------------------------------------------------------------------
// Transpose fc1_w (H, 2H) -> WT (2H, H)
// ---------------------------------------------------------------------------
__global__ void transpose_fc1(const float* __restrict__ w, float* __restrict__ wt)
{
    int idx = blockIdx.x * blockDim.x + threadIdx.x;
    int total = HDIM * 2 * HDIM;
    if (idx < total) {
        int r = idx / (2 * HDIM);
        int c = idx % (2 * HDIM);
        wt[(size_t)c * HDIM + r] = w[idx];
    }
}

// ---------------------------------------------------------------------------
// logits = log_softmax(Y @ lp_w^T + lp_b). 4 rows per warp, 32 rows/block.
// ---------------------------------------------------------------------------
__global__ __launch_bounds__(256)
void logits_kernel(const float* __restrict__ Y, const float* __restrict__ lp_w,
                   const float* __restrict__ lp_b, float* __restrict__ out)
{
    __shared__ float ws[AADIM * HDIM];
    __shared__ float bs[32];
    const int tid = threadIdx.x;
    for (int i = tid; i < AADIM * HDIM; i += blockDim.x) ws[i] = lp_w[i];
    if (tid < AADIM) bs[tid] = lp_b[tid];
    __syncthreads();

    const int warp = tid >> 5;
    const int lane = tid & 31;

    #pragma unroll
    for (int rr = 0; rr < 4; rr++) {
        const int row = blockIdx.x * 32 + warp * 4 + rr;   // row = t*B + b
        const int t = row / BDIM;
        const int b = row % BDIM;

        const float* y = Y + (size_t)row * HDIM;
        float yv[8];
        #pragma unroll
        for (int i = 0; i < 8; i++) yv[i] = y[lane + 32 * i];

        float lg[AADIM];
        #pragma unroll
        for (int a = 0; a < AADIM; a++) {
            float s = 0.f;
            #pragma unroll
            for (int i = 0; i < 8; i++) s += yv[i] * ws[a * HDIM + lane + 32 * i];
            #pragma unroll
            for (int off = 16; off > 0; off >>= 1)
                s += __shfl_xor_sync(0xFFFFFFFFu, s, off);
            lg[a] = s + bs[a];
        }

        float mx = lg[0];
        #pragma unroll
        for (int a = 1; a < AADIM; a++) mx = fmaxf(mx, lg[a]);
        float se = 0.f;
        #pragma unroll
        for (int a = 0; a < AADIM; a++) se += __expf(lg[a] - mx);
        float lse = mx + __logf(se);

        float myv = 0.f;
        #pragma unroll
        for (int a = 0; a < AADIM; a++) if (lane == a) myv = lg[a] - lse;
        if (lane < AADIM)
            out[((size_t)b * TDIM + t) * AADIM + lane] = myv;
    }
}

// ---------------------------------------------------------------------------
extern "C" void kernel_launch(void* const* d_in, const int* in_sizes, int n_in,
                              void* d_out, int out_size)
{
    const float* x     = (const float*)d_in[0];
    // d_in[1] = hidden (unused)
    const float* w_l0  = (const float*)d_in[2];
    const float* wc_l0 = (const float*)d_in[3];
    const float* b_l0  = (const float*)d_in[4];
    const float* w_l1  = (const float*)d_in[5];
    const float* wc_l1 = (const float*)d_in[6];
    const float* b_l1  = (const float*)d_in[7];
    const float* fc1_w = (const float*)d_in[8];
    const float* fc1_b = (const float*)d_in[9];
    const float* lp_w  = (const float*)d_in[10];
    const float* lp_b  = (const float*)d_in[11];
    float* out = (float*)d_out;

    float *pU, *pH0, *pH1, *pY, *pWT, *pWP0, *pWP1;
    cudaGetSymbolAddress((void**)&pU,   g_U);
    cudaGetSymbolAddress((void**)&pH0,  g_H0);
    cudaGetSymbolAddress((void**)&pH1,  g_H1);
    cudaGetSymbolAddress((void**)&pY,   g_Y);
    cudaGetSymbolAddress((void**)&pWT,  g_WT);
    cudaGetSymbolAddress((void**)&pWP0, g_WP0);
    cudaGetSymbolAddress((void**)&pWP1, g_WP1);

    // allow >48KB dynamic smem (idempotent)
    static bool attr_done = false;
    if (!attr_done) {
        cudaFuncSetAttribute(tf32_gemm<true>,
            cudaFuncAttributeMaxDynamicSharedMemorySize, GSMEM);
        cudaFuncSetAttribute(tf32_gemm<false>,
            cudaFuncAttributeMaxDynamicSharedMemorySize, GSMEM);
        attr_done = true;
    }

    const int M = TDIM * BDIM;      // 32768

    // prep: permute weights, transpose fc1
    permute_w<<<(DIN * 2048 + 255) / 256, 256>>>(w_l0, pWP0, DIN);
    permute_w<<<(2 * HDIM * 2048 + 255) / 256, 256>>>(w_l1, pWP1, 2 * HDIM);
    transpose_fc1<<<(HDIM * 2 * HDIM + 255) / 256, 256>>>(fc1_w, pWT);

    // GEMM1: U0 = x(T,B view) @ WP0  [32768 x 2048 x 256]
    {
        dim3 grid(2048 / 128, M / 128);
        tf32_gemm<true><<<grid, 128, GSMEM>>>(x, pWP0, pU, M, 2048, DIN, nullptr);
    }
    sru_scan_kernel<<<2 * BDIM * (HDIM / 64), 64>>>((const float4*)pU, wc_l0, b_l0, pH0);

    // GEMM2: U1 = H0 @ WP1  [32768 x 2048 x 512]
    {
        dim3 grid(2048 / 128, M / 128);
        tf32_gemm<false><<<grid, 128, GSMEM>>>(pH0, pWP1, pU, M, 2048, 2 * HDIM, nullptr);
    }
    sru_scan_kernel<<<2 * BDIM * (HDIM / 64), 64>>>((const float4*)pU, wc_l1, b_l1, pH1);

    // GEMM3: Y = H1 @ WT + fc1_b  [32768 x 256 x 512]
    {
        dim3 grid(HDIM / 128, M / 128);
        tf32_gemm<false><<<grid, 128, GSMEM>>>(pH1, pWT, pY, M, HDIM, 2 * HDIM, fc1_b);
    }

    // logits + log_softmax
    logits_kernel<<<M / 32, 256>>>(pY, lp_w, lp_b, out);
}